// round 8
// baseline (speedup 1.0000x reference)
#include <cuda_runtime.h>
#include <cuda_bf16.h>
#include <cstddef>

// Problem constants
#define BB 8
#define TT 16
#define HH 64
#define WW 64
#define CIN 32
#define FF 32
#define G4F 128
#define BN_EPS 1e-3f

// ======================= device scratch (no allocs) ========================
__device__ float g_xg[(size_t)BB * TT * HH * WW * G4F];
__device__ float g_h[2][(size_t)BB * HH * WW * FF];
__device__ float g_c[(size_t)BB * HH * WW * FF];
__device__ unsigned g_barb[BB * TT];     // per-batch, per-step counters

// ======================= helpers ===========================================
__device__ __forceinline__ float hsig(float x) {
    return __saturatef(fmaf(0.2f, x, 0.5f));
}
// fast tanh: exact at saturation, ~1e-6 rel error in between
__device__ __forceinline__ float ftanh(float x) {
    float e = __expf(2.f * x);
    return 1.f - 2.f / (e + 1.f);
}
__device__ __forceinline__ unsigned long long pack2(float v) {
    unsigned long long r;
    asm("mov.b64 %0, {%1, %1};" : "=l"(r) : "f"(v));
    return r;
}
__device__ __forceinline__ void ffma2(unsigned long long& d,
                                      unsigned long long a,
                                      unsigned long long b) {
    asm("fma.rn.f32x2 %0, %1, %2, %3;" : "=l"(d) : "l"(a), "l"(b), "l"(d));
}
__device__ __forceinline__ void unpack2(unsigned long long p, float& lo, float& hi) {
    asm("mov.b64 {%0, %1}, %2;" : "=f"(lo), "=f"(hi) : "l"(p));
}

// ===========================================================================
// xg kernel — the best-measured configuration (R2/R3 era, ~660us):
// 16x16 pixel tile, 1 px/thread, full weight staging, 78.5KB smem.
// grid: (16 tiles, 4 cout-chunks, 128 frames), block 256.
// ===========================================================================
#define XG_SIN_STRIDE 325
#define XG_SIN_FLOATS (32 * XG_SIN_STRIDE)   // 10400
#define XG_SW_FLOATS  (288 * 32)             // 9216
#define XG_SMEM ((XG_SIN_FLOATS + XG_SW_FLOATS) * 4)  // 78464

__global__ void __launch_bounds__(256) xg_conv_kernel(
    const float* __restrict__ x, const float* __restrict__ Wx,
    const float* __restrict__ b)
{
    extern __shared__ float sm[];
    float* s_in = sm;                 // [32][XG_SIN_STRIDE]
    float* s_w  = sm + XG_SIN_FLOATS; // [288][32]

    const int tile = blockIdx.x;      // 0..15
    const int cc   = blockIdx.y;      // cout chunk 0..3
    const int n    = blockIdx.z;      // frame 0..127
    const int ty0 = (tile >> 2) * 16;
    const int tx0 = (tile & 3) * 16;
    const int tid = threadIdx.x;

    const float* xin = x + (size_t)n * HH * WW * CIN;
    for (int i = tid; i < 18 * 18 * 32; i += 256) {
        int cin = i & 31;
        int p   = i >> 5;             // 0..323
        int py  = p / 18, px = p - py * 18;
        int gy = ty0 + py - 1, gx = tx0 + px - 1;
        float v = 0.f;
        if ((unsigned)gy < (unsigned)HH && (unsigned)gx < (unsigned)WW)
            v = xin[((size_t)gy * WW + gx) * CIN + cin];
        s_in[cin * XG_SIN_STRIDE + p] = v;
    }
    for (int i = tid; i < 288 * 32; i += 256) {
        int k = i >> 5, co = i & 31;
        s_w[i] = Wx[k * G4F + cc * 32 + co];
    }
    __syncthreads();

    const int py = tid >> 4, px = tid & 15;
    unsigned long long acc[16];
#pragma unroll
    for (int m = 0; m < 16; m++) acc[m] = 0ull;

#pragma unroll
    for (int dy = 0; dy < 3; dy++) {
#pragma unroll
        for (int dx = 0; dx < 3; dx++) {
            const float* inb = &s_in[(py + dy) * 18 + (px + dx)];
            const float* wb  = &s_w[(dy * 3 + dx) * 32 * 32];
#pragma unroll 4
            for (int cin = 0; cin < 32; cin++) {
                unsigned long long vv = pack2(inb[cin * XG_SIN_STRIDE]);
                const ulonglong2* w2 = (const ulonglong2*)(wb + cin * 32);
#pragma unroll
                for (int q = 0; q < 8; q++) {
                    ulonglong2 w = w2[q];
                    ffma2(acc[q * 2 + 0], vv, w.x);
                    ffma2(acc[q * 2 + 1], vv, w.y);
                }
            }
        }
    }

    float a[32];
#pragma unroll
    for (int m = 0; m < 16; m++) unpack2(acc[m], a[2 * m], a[2 * m + 1]);

    const int gy = ty0 + py, gx = tx0 + px;
    float* outp = &g_xg[(((size_t)n * HH * WW) + (size_t)gy * WW + gx) * G4F + cc * 32];
#pragma unroll
    for (int q = 0; q < 8; q++) {
        float4 bv = *(const float4*)&b[cc * 32 + q * 4];
        float4 o;
        o.x = a[q * 4 + 0] + bv.x;
        o.y = a[q * 4 + 1] + bv.y;
        o.z = a[q * 4 + 2] + bv.z;
        o.w = a[q * 4 + 3] + bv.w;
        ((float4*)outp)[q] = o;
    }
}

// ===========================================================================
// LSTM: persistent, R4 config (tap-streamed weights, 86.5KB smem, 2 CTA/SM),
// now with PER-BATCH barriers (32 CTAs each) so independent sequences drift
// and co-resident CTAs hide each other's waits. Fast tanh in epilogue.
// ===========================================================================
#define TW 32
#define TH 16
#define IN_ROWS 18
#define IN_COLS 34
#define ROW_STRIDE (32 * IN_COLS)
#define SIN_FLOATS (IN_ROWS * ROW_STRIDE)     // 19584
#define SWBUF_FLOATS (2 * 32 * 32)            // 2048
#define LS_SMEM ((SIN_FLOATS + SWBUF_FLOATS) * 4)  // 86528
#define LSTM_GRID 256
#define BATCH_CTAS 32

__device__ __forceinline__ void conv_tap(
    const float* __restrict__ s_in, const float* __restrict__ wb,
    int pr, int px, int dy, int dx,
    unsigned long long* acc0, unsigned long long* acc1)
{
    const float* i0 = &s_in[(pr + dy) * ROW_STRIDE + (px + dx)];
    const float* i1 = i0 + 8 * ROW_STRIDE;
#pragma unroll 4
    for (int cin = 0; cin < 32; cin++) {
        unsigned long long v0 = pack2(i0[cin * IN_COLS]);
        unsigned long long v1 = pack2(i1[cin * IN_COLS]);
        const ulonglong2* w2 = (const ulonglong2*)(wb + cin * 32);
#pragma unroll
        for (int q = 0; q < 8; q++) {
            ulonglong2 w = w2[q];
            ffma2(acc0[q * 2 + 0], v0, w.x);
            ffma2(acc0[q * 2 + 1], v0, w.y);
            ffma2(acc1[q * 2 + 0], v1, w.x);
            ffma2(acc1[q * 2 + 1], v1, w.y);
        }
    }
}

__device__ __forceinline__ void load_tap_lstm(
    float* __restrict__ dst, const float* __restrict__ Wh, int kk, int fc, int tid)
{
    int cin = tid >> 3, col0 = (tid & 7) * 4;
    int cout0 = (col0 >> 3) * 32 + fc * 8 + (col0 & 7);
    float4 w = *(const float4*)&Wh[((size_t)(kk * CIN + cin)) * G4F + cout0];
    *(float4*)&dst[cin * 32 + col0] = w;
}

__device__ __forceinline__ void load_h_tile(
    float* __restrict__ s_in, const float* __restrict__ src,
    int ty0, int tx0, int tid)
{
    for (int i = tid; i < IN_ROWS * IN_COLS * 32; i += 256) {
        int cin = i & 31;
        int p   = i >> 5;
        int row = p / IN_COLS, col = p - row * IN_COLS;
        int gy = ty0 + row - 1, gx = tx0 + col - 1;
        float v = 0.f;
        if ((unsigned)gy < (unsigned)HH && (unsigned)gx < (unsigned)WW)
            v = __ldcv(&src[((size_t)gy * WW + gx) * FF + cin]);
        s_in[(row * 32 + cin) * IN_COLS + col] = v;
    }
}

__global__ void bar_reset_kernel() {
    if (threadIdx.x < BB * TT) g_barb[threadIdx.x] = 0u;
}

__global__ void __launch_bounds__(256, 2) lstm_persistent(
    const float* __restrict__ Wh,
    const float* __restrict__ gamma, const float* __restrict__ beta,
    const float* __restrict__ mmean, const float* __restrict__ mvar,
    float* __restrict__ out)
{
    extern __shared__ float sm[];
    float* s_in = sm;
    float* s_w  = sm + SIN_FLOATS;

    const int cta  = blockIdx.x;
    const int tile = cta & 7;
    const int fc   = (cta >> 3) & 3;
    const int bb   = cta >> 5;            // batch item: 32 CTAs per batch
    const int tx0 = (tile & 1) * TW;
    const int ty0 = (tile >> 1) * TH;
    const int tid = threadIdx.x;
    const int px = tid & 31, pr = tid >> 5;
    const int gx = tx0 + px;
    const int gy0 = ty0 + pr;

    float inv[8], off[8];
#pragma unroll
    for (int j = 0; j < 8; j++) {
        int f = fc * 8 + j;
        inv[j] = gamma[f] * rsqrtf(mvar[f] + BN_EPS);
        off[j] = beta[f] - mmean[f] * inv[j];
    }

    for (int t = 0; t < TT; t++) {
        unsigned long long acc0[16], acc1[16];
#pragma unroll
        for (int m = 0; m < 16; m++) { acc0[m] = 0ull; acc1[m] = 0ull; }

        if (t > 0) {
            const float* hin = g_h[(t + 1) & 1] + (size_t)bb * HH * WW * FF;
            load_h_tile(s_in, hin, ty0, tx0, tid);
            load_tap_lstm(s_w, Wh, 0, fc, tid);
            __syncthreads();
#pragma unroll
            for (int tap = 0; tap < 9; tap++) {
                if (tap < 8)
                    load_tap_lstm(&s_w[((tap + 1) & 1) * 1024], Wh, tap + 1, fc, tid);
                conv_tap(s_in, &s_w[(tap & 1) * 1024], pr, px, tap / 3, tap % 3,
                         acc0, acc1);
                __syncthreads();
            }
        }

        float a0[32], a1[32];
#pragma unroll
        for (int m = 0; m < 16; m++) {
            unpack2(acc0[m], a0[2 * m], a0[2 * m + 1]);
            unpack2(acc1[m], a1[2 * m], a1[2 * m + 1]);
        }

#pragma unroll
        for (int p = 0; p < 2; p++) {
            const float* a = p ? a1 : a0;
            const int gy = gy0 + p * 8;
            const size_t pix   = (size_t)bb * HH * WW + (size_t)gy * WW + gx;
            const size_t frame = (size_t)(bb * TT + t) * HH * WW + (size_t)gy * WW + gx;
            const float* xgp = &g_xg[frame * G4F];
            float* cst = &g_c[pix * FF + fc * 8];
            float* hst = &g_h[t & 1][pix * FF + fc * 8];
            float* op  = &out[frame * FF + fc * 8];

            float coldv[8] = {0,0,0,0,0,0,0,0};
            if (t > 0) {
                float4 c0 = ((const float4*)cst)[0];
                float4 c1 = ((const float4*)cst)[1];
                coldv[0]=c0.x; coldv[1]=c0.y; coldv[2]=c0.z; coldv[3]=c0.w;
                coldv[4]=c1.x; coldv[5]=c1.y; coldv[6]=c1.z; coldv[7]=c1.w;
            }

            float cv[8], hv[8], ov[8];
#pragma unroll
            for (int j = 0; j < 8; j++) {
                int f = fc * 8 + j;
                float gi = a[0 * 8 + j] + __ldg(&xgp[0 * 32 + f]);
                float gf = a[1 * 8 + j] + __ldg(&xgp[1 * 32 + f]);
                float gc = a[2 * 8 + j] + __ldg(&xgp[2 * 32 + f]);
                float go = a[3 * 8 + j] + __ldg(&xgp[3 * 32 + f]);
                gi = hsig(gi); gf = hsig(gf); go = hsig(go);
                float cn = gf * coldv[j] + gi * ftanh(gc);
                float h  = go * ftanh(cn);
                cv[j] = cn; hv[j] = h;
                ov[j] = fmaf(h, inv[j], off[j]);
            }
            ((float4*)cst)[0] = make_float4(cv[0], cv[1], cv[2], cv[3]);
            ((float4*)cst)[1] = make_float4(cv[4], cv[5], cv[6], cv[7]);
            ((float4*)hst)[0] = make_float4(hv[0], hv[1], hv[2], hv[3]);
            ((float4*)hst)[1] = make_float4(hv[4], hv[5], hv[6], hv[7]);
            ((float4*)op)[0]  = make_float4(ov[0], ov[1], ov[2], ov[3]);
            ((float4*)op)[1]  = make_float4(ov[4], ov[5], ov[6], ov[7]);
        }

        // PER-BATCH barrier: only the 32 CTAs of this batch item sync.
        if (t < TT - 1) {
            __threadfence();
            __syncthreads();
            if (tid == 0) {
                unsigned* ctr = &g_barb[bb * TT + t];
                atomicAdd(ctr, 1u);
                while (*((volatile unsigned*)ctr) < (unsigned)BATCH_CTAS)
                    __nanosleep(64);
            }
            __syncthreads();
            __threadfence();
        }
    }
}

// ===========================================================================
extern "C" void kernel_launch(void* const* d_in, const int* in_sizes, int n_in,
                              void* d_out, int out_size)
{
    const float* x     = (const float*)d_in[0];
    const float* Wx    = (const float*)d_in[1];
    const float* Wh    = (const float*)d_in[2];
    const float* b     = (const float*)d_in[3];
    const float* gamma = (const float*)d_in[4];
    const float* beta  = (const float*)d_in[5];
    const float* mmean = (const float*)d_in[6];
    const float* mvar  = (const float*)d_in[7];
    float* out = (float*)d_out;

    cudaFuncSetAttribute(xg_conv_kernel,
        cudaFuncAttributeMaxDynamicSharedMemorySize, XG_SMEM);
    cudaFuncSetAttribute(lstm_persistent,
        cudaFuncAttributeMaxDynamicSharedMemorySize, LS_SMEM);

    // 1) input-to-gate conv for all frames (best-measured config)
    {
        dim3 grid(16, 4, BB * TT);
        xg_conv_kernel<<<grid, 256, XG_SMEM>>>(x, Wx, b);
    }
    // 2) persistent recurrence with per-batch barriers
    bar_reset_kernel<<<1, 128>>>();
    lstm_persistent<<<LSTM_GRID, 256, LS_SMEM>>>(
        Wh, gamma, beta, mmean, mvar, out);
}

// round 9
// speedup vs baseline: 1.2373x; 1.2373x over previous
#include <cuda_runtime.h>
#include <cuda_bf16.h>
#include <cstddef>

// Problem constants
#define BB 8
#define TT 16
#define HH 64
#define WW 64
#define CIN 32
#define FF 32
#define G4F 128
#define BN_EPS 1e-3f

// ===== geometry shared by both kernels: 32x16 tile, 2 px/thread ===========
#define TW 32
#define TH 16
#define IN_ROWS 18
#define IN_COLS 34
#define ROW_STRIDE (32 * IN_COLS)
#define SIN_FLOATS (IN_ROWS * ROW_STRIDE)       // 19584

// xg: full weight staging (measured 662us in R3)
#define XG_SW_FLOATS (288 * 32)                 // 9216
#define XG_SMEM ((SIN_FLOATS + XG_SW_FLOATS) * 4)   // 115200

// lstm: tap-streamed weights (measured ~1303us in R5 decomposition)
#define SWBUF_FLOATS (2 * 32 * 32)              // 2048
#define LS_SMEM ((SIN_FLOATS + SWBUF_FLOATS) * 4)   // 86528
#define LSTM_GRID 256

// ======================= device scratch (no allocs) ========================
__device__ float g_xg[(size_t)BB * TT * HH * WW * G4F];
__device__ float g_h[2][(size_t)BB * HH * WW * FF];
__device__ float g_c[(size_t)BB * HH * WW * FF];
__device__ unsigned g_bar[TT];

// ======================= helpers ===========================================
__device__ __forceinline__ float hsig(float x) {
    return __saturatef(fmaf(0.2f, x, 0.5f));
}
__device__ __forceinline__ unsigned long long pack2(float v) {
    unsigned long long r;
    asm("mov.b64 %0, {%1, %1};" : "=l"(r) : "f"(v));
    return r;
}
__device__ __forceinline__ void ffma2(unsigned long long& d,
                                      unsigned long long a,
                                      unsigned long long b) {
    asm("fma.rn.f32x2 %0, %1, %2, %3;" : "=l"(d) : "l"(a), "l"(b), "l"(d));
}
__device__ __forceinline__ void unpack2(unsigned long long p, float& lo, float& hi) {
    asm("mov.b64 {%0, %1}, %2;" : "=f"(lo), "=f"(hi) : "l"(p));
}

// Full 3x3 conv, weights fully staged in smem (xg path).
__device__ __forceinline__ void conv_core(
    const float* __restrict__ s_in, const float* __restrict__ s_w,
    int pr, int px, unsigned long long* acc0, unsigned long long* acc1)
{
#pragma unroll
    for (int dy = 0; dy < 3; dy++) {
#pragma unroll
        for (int dx = 0; dx < 3; dx++) {
            const float* i0 = &s_in[(pr + dy) * ROW_STRIDE + (px + dx)];
            const float* i1 = i0 + 8 * ROW_STRIDE;
            const float* wb = &s_w[(dy * 3 + dx) * 32 * 32];
#pragma unroll 4
            for (int cin = 0; cin < 32; cin++) {
                unsigned long long v0 = pack2(i0[cin * IN_COLS]);
                unsigned long long v1 = pack2(i1[cin * IN_COLS]);
                const ulonglong2* w2 = (const ulonglong2*)(wb + cin * 32);
#pragma unroll
                for (int q = 0; q < 8; q++) {
                    ulonglong2 w = w2[q];
                    ffma2(acc0[q * 2 + 0], v0, w.x);
                    ffma2(acc0[q * 2 + 1], v0, w.y);
                    ffma2(acc1[q * 2 + 0], v1, w.x);
                    ffma2(acc1[q * 2 + 1], v1, w.y);
                }
            }
        }
    }
}

// One 3x3 tap over 32 cin (lstm tap-streamed path).
__device__ __forceinline__ void conv_tap(
    const float* __restrict__ s_in, const float* __restrict__ wb,
    int pr, int px, int dy, int dx,
    unsigned long long* acc0, unsigned long long* acc1)
{
    const float* i0 = &s_in[(pr + dy) * ROW_STRIDE + (px + dx)];
    const float* i1 = i0 + 8 * ROW_STRIDE;
#pragma unroll 4
    for (int cin = 0; cin < 32; cin++) {
        unsigned long long v0 = pack2(i0[cin * IN_COLS]);
        unsigned long long v1 = pack2(i1[cin * IN_COLS]);
        const ulonglong2* w2 = (const ulonglong2*)(wb + cin * 32);
#pragma unroll
        for (int q = 0; q < 8; q++) {
            ulonglong2 w = w2[q];
            ffma2(acc0[q * 2 + 0], v0, w.x);
            ffma2(acc0[q * 2 + 1], v0, w.y);
            ffma2(acc1[q * 2 + 0], v1, w.x);
            ffma2(acc1[q * 2 + 1], v1, w.y);
        }
    }
}

// Load 18x34x32 input tile into smem [row][cin][col].
template <bool CV>
__device__ __forceinline__ void load_input_tile(
    float* __restrict__ s_in, const float* __restrict__ src,
    int ty0, int tx0, int tid, int ch_stride)
{
    for (int i = tid; i < IN_ROWS * IN_COLS * 32; i += 256) {
        int cin = i & 31;
        int p   = i >> 5;
        int row = p / IN_COLS, col = p - row * IN_COLS;
        int gy = ty0 + row - 1, gx = tx0 + col - 1;
        float v = 0.f;
        if ((unsigned)gy < (unsigned)HH && (unsigned)gx < (unsigned)WW) {
            const float* ap = &src[((size_t)gy * WW + gx) * ch_stride + cin];
            v = CV ? __ldcv(ap) : __ldg(ap);
        }
        s_in[(row * 32 + cin) * IN_COLS + col] = v;
    }
}

// ---------------------------------------------------------------------------
// Kernel 1: xg = conv(x, Wx) + b. grid (8,4,128), block 256. (R3-measured 662us)
// ---------------------------------------------------------------------------
__global__ void __launch_bounds__(256, 2) xg_conv_kernel(
    const float* __restrict__ x, const float* __restrict__ Wx,
    const float* __restrict__ b)
{
    extern __shared__ float sm[];
    float* s_in = sm;
    float* s_w  = sm + SIN_FLOATS;

    const int tile = blockIdx.x;       // 0..7
    const int cc   = blockIdx.y;       // cout chunk 0..3
    const int n    = blockIdx.z;       // frame
    const int tx0 = (tile & 1) * TW;
    const int ty0 = (tile >> 1) * TH;
    const int tid = threadIdx.x;

    load_input_tile<false>(s_in, x + (size_t)n * HH * WW * CIN, ty0, tx0, tid, CIN);
    for (int i = tid; i < 288 * 32; i += 256) {
        int k = i >> 5, co = i & 31;
        s_w[i] = Wx[k * G4F + cc * 32 + co];
    }
    __syncthreads();

    const int px = tid & 31, pr = tid >> 5;
    unsigned long long acc0[16], acc1[16];
#pragma unroll
    for (int m = 0; m < 16; m++) { acc0[m] = 0ull; acc1[m] = 0ull; }

    conv_core(s_in, s_w, pr, px, acc0, acc1);

    float a0[32], a1[32];
#pragma unroll
    for (int m = 0; m < 16; m++) {
        unpack2(acc0[m], a0[2 * m], a0[2 * m + 1]);
        unpack2(acc1[m], a1[2 * m], a1[2 * m + 1]);
    }

    const int gx = tx0 + px;
    const int gy0 = ty0 + pr, gy1 = gy0 + 8;
    float* o0 = &g_xg[(((size_t)n * HH + gy0) * WW + gx) * G4F + cc * 32];
    float* o1 = &g_xg[(((size_t)n * HH + gy1) * WW + gx) * G4F + cc * 32];
#pragma unroll
    for (int q = 0; q < 8; q++) {
        float4 bv = *(const float4*)&b[cc * 32 + q * 4];
        ((float4*)o0)[q] = make_float4(a0[q*4+0]+bv.x, a0[q*4+1]+bv.y,
                                       a0[q*4+2]+bv.z, a0[q*4+3]+bv.w);
        ((float4*)o1)[q] = make_float4(a1[q*4+0]+bv.x, a1[q*4+1]+bv.y,
                                       a1[q*4+2]+bv.z, a1[q*4+3]+bv.w);
    }
}

// ---------------------------------------------------------------------------
__global__ void bar_reset_kernel() {
    if (threadIdx.x < TT) g_bar[threadIdx.x] = 0u;
}

__device__ __forceinline__ void load_tap_lstm(
    float* __restrict__ dst, const float* __restrict__ Wh, int kk, int fc, int tid)
{
    int cin = tid >> 3, col0 = (tid & 7) * 4;
    int cout0 = (col0 >> 3) * 32 + fc * 8 + (col0 & 7);
    float4 w = *(const float4*)&Wh[((size_t)(kk * CIN + cin)) * G4F + cout0];
    *(float4*)&dst[cin * 32 + col0] = w;
}

// ---------------------------------------------------------------------------
// Kernel 2: persistent LSTM, R4 config exactly (global barrier, tanhf).
// ---------------------------------------------------------------------------
__global__ void __launch_bounds__(256, 2) lstm_persistent(
    const float* __restrict__ Wh,
    const float* __restrict__ gamma, const float* __restrict__ beta,
    const float* __restrict__ mmean, const float* __restrict__ mvar,
    float* __restrict__ out)
{
    extern __shared__ float sm[];
    float* s_in = sm;
    float* s_w  = sm + SIN_FLOATS;

    const int cta  = blockIdx.x;
    const int tile = cta & 7;
    const int fc   = (cta >> 3) & 3;
    const int bb   = cta >> 5;
    const int tx0 = (tile & 1) * TW;
    const int ty0 = (tile >> 1) * TH;
    const int tid = threadIdx.x;
    const int px = tid & 31, pr = tid >> 5;
    const int gx = tx0 + px;
    const int gy0 = ty0 + pr;

    float inv[8], off[8];
#pragma unroll
    for (int j = 0; j < 8; j++) {
        int f = fc * 8 + j;
        inv[j] = gamma[f] * rsqrtf(mvar[f] + BN_EPS);
        off[j] = beta[f] - mmean[f] * inv[j];
    }

    for (int t = 0; t < TT; t++) {
        unsigned long long acc0[16], acc1[16];
#pragma unroll
        for (int m = 0; m < 16; m++) { acc0[m] = 0ull; acc1[m] = 0ull; }

        if (t > 0) {
            const float* hin = g_h[(t + 1) & 1] + (size_t)bb * HH * WW * FF;
            load_input_tile<true>(s_in, hin, ty0, tx0, tid, FF);
            load_tap_lstm(s_w, Wh, 0, fc, tid);
            __syncthreads();
#pragma unroll
            for (int tap = 0; tap < 9; tap++) {
                if (tap < 8)
                    load_tap_lstm(&s_w[((tap + 1) & 1) * 1024], Wh, tap + 1, fc, tid);
                conv_tap(s_in, &s_w[(tap & 1) * 1024], pr, px, tap / 3, tap % 3,
                         acc0, acc1);
                __syncthreads();
            }
        }

        float a0[32], a1[32];
#pragma unroll
        for (int m = 0; m < 16; m++) {
            unpack2(acc0[m], a0[2 * m], a0[2 * m + 1]);
            unpack2(acc1[m], a1[2 * m], a1[2 * m + 1]);
        }

#pragma unroll
        for (int p = 0; p < 2; p++) {
            const float* a = p ? a1 : a0;
            const int gy = gy0 + p * 8;
            const size_t pix   = (size_t)bb * HH * WW + (size_t)gy * WW + gx;
            const size_t frame = (size_t)(bb * TT + t) * HH * WW + (size_t)gy * WW + gx;
            const float* xgp = &g_xg[frame * G4F];
            float* cst = &g_c[pix * FF + fc * 8];
            float* hst = &g_h[t & 1][pix * FF + fc * 8];
            float* op  = &out[frame * FF + fc * 8];

            float coldv[8] = {0,0,0,0,0,0,0,0};
            if (t > 0) {
                float4 c0 = ((const float4*)cst)[0];
                float4 c1 = ((const float4*)cst)[1];
                coldv[0]=c0.x; coldv[1]=c0.y; coldv[2]=c0.z; coldv[3]=c0.w;
                coldv[4]=c1.x; coldv[5]=c1.y; coldv[6]=c1.z; coldv[7]=c1.w;
            }

            float cv[8], hv[8], ov[8];
#pragma unroll
            for (int j = 0; j < 8; j++) {
                int f = fc * 8 + j;
                float gi = a[0 * 8 + j] + __ldg(&xgp[0 * 32 + f]);
                float gf = a[1 * 8 + j] + __ldg(&xgp[1 * 32 + f]);
                float gc = a[2 * 8 + j] + __ldg(&xgp[2 * 32 + f]);
                float go = a[3 * 8 + j] + __ldg(&xgp[3 * 32 + f]);
                gi = hsig(gi); gf = hsig(gf); go = hsig(go);
                float cn = gf * coldv[j] + gi * tanhf(gc);
                float h  = go * tanhf(cn);
                cv[j] = cn; hv[j] = h;
                ov[j] = fmaf(h, inv[j], off[j]);
            }
            ((float4*)cst)[0] = make_float4(cv[0], cv[1], cv[2], cv[3]);
            ((float4*)cst)[1] = make_float4(cv[4], cv[5], cv[6], cv[7]);
            ((float4*)hst)[0] = make_float4(hv[0], hv[1], hv[2], hv[3]);
            ((float4*)hst)[1] = make_float4(hv[4], hv[5], hv[6], hv[7]);
            ((float4*)op)[0]  = make_float4(ov[0], ov[1], ov[2], ov[3]);
            ((float4*)op)[1]  = make_float4(ov[4], ov[5], ov[6], ov[7]);
        }

        if (t < TT - 1) {
            __threadfence();
            __syncthreads();
            if (tid == 0) {
                atomicAdd(&g_bar[t], 1u);
                while (*((volatile unsigned*)&g_bar[t]) < (unsigned)LSTM_GRID)
                    __nanosleep(64);
            }
            __syncthreads();
            __threadfence();
        }
    }
}

// ===========================================================================
extern "C" void kernel_launch(void* const* d_in, const int* in_sizes, int n_in,
                              void* d_out, int out_size)
{
    const float* x     = (const float*)d_in[0];
    const float* Wx    = (const float*)d_in[1];
    const float* Wh    = (const float*)d_in[2];
    const float* b     = (const float*)d_in[3];
    const float* gamma = (const float*)d_in[4];
    const float* beta  = (const float*)d_in[5];
    const float* mmean = (const float*)d_in[6];
    const float* mvar  = (const float*)d_in[7];
    float* out = (float*)d_out;

    cudaFuncSetAttribute(xg_conv_kernel,
        cudaFuncAttributeMaxDynamicSharedMemorySize, XG_SMEM);
    cudaFuncSetAttribute(lstm_persistent,
        cudaFuncAttributeMaxDynamicSharedMemorySize, LS_SMEM);

    // 1) input-to-gate conv (R3-measured best config: 662us)
    {
        dim3 grid(8, 4, BB * TT);
        xg_conv_kernel<<<grid, 256, XG_SMEM>>>(x, Wx, b);
    }
    // 2) persistent recurrence (R4-measured best config: ~1303us)
    bar_reset_kernel<<<1, 32>>>();
    lstm_persistent<<<LSTM_GRID, 256, LS_SMEM>>>(
        Wh, gamma, beta, mmean, mvar, out);
}

// round 10
// speedup vs baseline: 1.3132x; 1.0614x over previous
#include <cuda_runtime.h>
#include <cuda_bf16.h>
#include <cstddef>

// Problem constants
#define BB 8
#define TT 16
#define HH 64
#define WW 64
#define CIN 32
#define FF 32
#define G4F 128
#define BN_EPS 1e-3f

// Tile: 32 wide x 16 tall, 256 threads, 2 px/thread (rows pr, pr+8)
#define TW 32
#define TH 16
#define IN_ROWS 18
#define IN_COLS 34
#define ROW_STRIDE (32 * IN_COLS)
#define SIN_FLOATS (IN_ROWS * ROW_STRIDE)     // 19584
#define SWBUF_FLOATS (2 * 32 * 32)            // 2048 (double-buffered tap)
#define SMEM_BYTES ((SIN_FLOATS + SWBUF_FLOATS) * 4)  // 86528 -> 2 CTA/SM

#define LSTM_GRID 256

// ======================= device scratch (no allocs) ========================
__device__ float g_xg[(size_t)BB * TT * HH * WW * G4F];
// h state TRANSPOSED: [2][b][f][y][x] — internal layout, coalesced row loads
__device__ float g_h[2][(size_t)BB * FF * HH * WW];
__device__ float g_c[(size_t)BB * HH * WW * FF];
__device__ unsigned g_bar[TT];

// ======================= helpers ===========================================
__device__ __forceinline__ float hsig(float x) {
    return __saturatef(fmaf(0.2f, x, 0.5f));
}
__device__ __forceinline__ unsigned long long pack2(float v) {
    unsigned long long r;
    asm("mov.b64 %0, {%1, %1};" : "=l"(r) : "f"(v));
    return r;
}
__device__ __forceinline__ void ffma2(unsigned long long& d,
                                      unsigned long long a,
                                      unsigned long long b) {
    asm("fma.rn.f32x2 %0, %1, %2, %3;" : "=l"(d) : "l"(a), "l"(b), "l"(d));
}
__device__ __forceinline__ void unpack2(unsigned long long p, float& lo, float& hi) {
    asm("mov.b64 {%0, %1}, %2;" : "=f"(lo), "=f"(hi) : "l"(p));
}

// One 3x3 tap (dy,dx) over 32 cin for 2 pixels, 32 couts. (R4-proven core)
__device__ __forceinline__ void conv_tap(
    const float* __restrict__ s_in, const float* __restrict__ wb,
    int pr, int px, int dy, int dx,
    unsigned long long* acc0, unsigned long long* acc1)
{
    const float* i0 = &s_in[(pr + dy) * ROW_STRIDE + (px + dx)];
    const float* i1 = i0 + 8 * ROW_STRIDE;
#pragma unroll 4
    for (int cin = 0; cin < 32; cin++) {
        unsigned long long v0 = pack2(i0[cin * IN_COLS]);
        unsigned long long v1 = pack2(i1[cin * IN_COLS]);
        const ulonglong2* w2 = (const ulonglong2*)(wb + cin * 32);
#pragma unroll
        for (int q = 0; q < 8; q++) {
            ulonglong2 w = w2[q];
            ffma2(acc0[q * 2 + 0], v0, w.x);
            ffma2(acc0[q * 2 + 1], v0, w.y);
            ffma2(acc1[q * 2 + 0], v1, w.x);
            ffma2(acc1[q * 2 + 1], v1, w.y);
        }
    }
}

// Tap weight loaders: 1024 floats, 1 float4 per thread.
__device__ __forceinline__ void load_tap_xg(
    float* __restrict__ dst, const float* __restrict__ Wx, int kk, int cc, int tid)
{
    int cin = tid >> 3, col0 = (tid & 7) * 4;
    float4 w = *(const float4*)&Wx[((size_t)(kk * CIN + cin)) * G4F + cc * 32 + col0];
    *(float4*)&dst[cin * 32 + col0] = w;
}
__device__ __forceinline__ void load_tap_lstm(
    float* __restrict__ dst, const float* __restrict__ Wh, int kk, int fc, int tid)
{
    int cin = tid >> 3, col0 = (tid & 7) * 4;
    int cout0 = (col0 >> 3) * 32 + fc * 8 + (col0 & 7);
    float4 w = *(const float4*)&Wh[((size_t)(kk * CIN + cin)) * G4F + cout0];
    *(float4*)&dst[cin * 32 + col0] = w;
}

// x tile loader: [y][x][cin] gmem, float4 along cin (4x fewer LDG).
__device__ __forceinline__ void load_x_tile(
    float* __restrict__ s_in, const float* __restrict__ src,
    int ty0, int tx0, int tid)
{
    // 612 positions x 8 cin-quads = 4896 float4 loads
    for (int j = tid; j < 612 * 8; j += 256) {
        int c4 = j & 7;
        int p  = j >> 3;               // 0..611
        int row = p / IN_COLS, col = p - row * IN_COLS;
        int gy = ty0 + row - 1, gx = tx0 + col - 1;
        float4 v = make_float4(0.f, 0.f, 0.f, 0.f);
        if ((unsigned)gy < (unsigned)HH && (unsigned)gx < (unsigned)WW)
            v = __ldg((const float4*)&src[((size_t)gy * WW + gx) * CIN + c4 * 4]);
        float* d = &s_in[(row * 32 + c4 * 4) * IN_COLS + col];
        d[0 * IN_COLS] = v.x;
        d[1 * IN_COLS] = v.y;
        d[2 * IN_COLS] = v.z;
        d[3 * IN_COLS] = v.w;
    }
}

// h tile loader from TRANSPOSED layout [f][y][x]: aligned float4 row loads.
__device__ __forceinline__ void load_h_tile(
    float* __restrict__ s_in, const float* __restrict__ src,
    int ty0, int tx0, int tid)
{
    // main body: 18 rows x 32 cin x 8 float4 covering gx tx0..tx0+31
    // -> smem cols 1..32
    for (int j = tid; j < 18 * 32 * 8; j += 256) {
        int c4  = j & 7;
        int cin = (j >> 3) & 31;
        int row = j >> 8;              // 0..17
        int gy = ty0 + row - 1;
        int gx0 = tx0 + c4 * 4;        // aligned, always in [0,64)
        float4 v = make_float4(0.f, 0.f, 0.f, 0.f);
        if ((unsigned)gy < (unsigned)HH)
            v = __ldcv((const float4*)&src[((size_t)cin * HH + gy) * WW + gx0]);
        float* d = &s_in[(row * 32 + cin) * IN_COLS + (c4 * 4 + 1)];
        d[0] = v.x; d[1] = v.y; d[2] = v.z; d[3] = v.w;
    }
    // edge columns: smem col 0 (gx=tx0-1) and col 33 (gx=tx0+32)
    for (int j = tid; j < 18 * 32 * 2; j += 256) {
        int e   = j & 1;
        int cin = (j >> 1) & 31;
        int row = j >> 6;              // 0..17
        int gy = ty0 + row - 1;
        int gx = e ? (tx0 + 32) : (tx0 - 1);
        float v = 0.f;
        if ((unsigned)gy < (unsigned)HH && (unsigned)gx < (unsigned)WW)
            v = __ldcv(&src[((size_t)cin * HH + gy) * WW + gx]);
        s_in[(row * 32 + cin) * IN_COLS + (e ? 33 : 0)] = v;
    }
}

// ---------------------------------------------------------------------------
// Kernel 1: xg = conv(x, Wx) + b (R4 tap-streamed config, vectorized loader).
// grid (8,4,128), block 256.
// ---------------------------------------------------------------------------
__global__ void __launch_bounds__(256, 2) xg_conv_kernel(
    const float* __restrict__ x, const float* __restrict__ Wx,
    const float* __restrict__ b)
{
    extern __shared__ float sm[];
    float* s_in = sm;
    float* s_w  = sm + SIN_FLOATS;     // 2 buffers of 1024 floats

    const int tile = blockIdx.x;
    const int cc   = blockIdx.y;
    const int n    = blockIdx.z;
    const int tx0 = (tile & 1) * TW;
    const int ty0 = (tile >> 1) * TH;
    const int tid = threadIdx.x;

    load_x_tile(s_in, x + (size_t)n * HH * WW * CIN, ty0, tx0, tid);
    load_tap_xg(s_w, Wx, 0, cc, tid);
    __syncthreads();

    const int px = tid & 31, pr = tid >> 5;
    unsigned long long acc0[16], acc1[16];
#pragma unroll
    for (int m = 0; m < 16; m++) { acc0[m] = 0ull; acc1[m] = 0ull; }

#pragma unroll
    for (int tap = 0; tap < 9; tap++) {
        if (tap < 8)
            load_tap_xg(&s_w[((tap + 1) & 1) * 1024], Wx, tap + 1, cc, tid);
        conv_tap(s_in, &s_w[(tap & 1) * 1024], pr, px, tap / 3, tap % 3, acc0, acc1);
        __syncthreads();
    }

    float a0[32], a1[32];
#pragma unroll
    for (int m = 0; m < 16; m++) {
        unpack2(acc0[m], a0[2 * m], a0[2 * m + 1]);
        unpack2(acc1[m], a1[2 * m], a1[2 * m + 1]);
    }

    const int gx = tx0 + px;
    const int gy0 = ty0 + pr, gy1 = gy0 + 8;
    float* o0 = &g_xg[(((size_t)n * HH + gy0) * WW + gx) * G4F + cc * 32];
    float* o1 = &g_xg[(((size_t)n * HH + gy1) * WW + gx) * G4F + cc * 32];
#pragma unroll
    for (int q = 0; q < 8; q++) {
        float4 bv = *(const float4*)&b[cc * 32 + q * 4];
        ((float4*)o0)[q] = make_float4(a0[q*4+0]+bv.x, a0[q*4+1]+bv.y,
                                       a0[q*4+2]+bv.z, a0[q*4+3]+bv.w);
        ((float4*)o1)[q] = make_float4(a1[q*4+0]+bv.x, a1[q*4+1]+bv.y,
                                       a1[q*4+2]+bv.z, a1[q*4+3]+bv.w);
    }
}

// ---------------------------------------------------------------------------
__global__ void bar_reset_kernel() {
    if (threadIdx.x < TT) g_bar[threadIdx.x] = 0u;
}

// ---------------------------------------------------------------------------
// Kernel 2: persistent LSTM (R4 config) with transposed h state.
// grid = 256 CTAs (2 CTA/SM co-resident). block 256, 2 px/thread.
// ---------------------------------------------------------------------------
__global__ void __launch_bounds__(256, 2) lstm_persistent(
    const float* __restrict__ Wh,
    const float* __restrict__ gamma, const float* __restrict__ beta,
    const float* __restrict__ mmean, const float* __restrict__ mvar,
    float* __restrict__ out)
{
    extern __shared__ float sm[];
    float* s_in = sm;
    float* s_w  = sm + SIN_FLOATS;

    const int cta  = blockIdx.x;
    const int tile = cta & 7;
    const int fc   = (cta >> 3) & 3;
    const int bb   = cta >> 5;
    const int tx0 = (tile & 1) * TW;
    const int ty0 = (tile >> 1) * TH;
    const int tid = threadIdx.x;
    const int px = tid & 31, pr = tid >> 5;
    const int gx = tx0 + px;
    const int gy0 = ty0 + pr;

    float inv[8], off[8];
#pragma unroll
    for (int j = 0; j < 8; j++) {
        int f = fc * 8 + j;
        inv[j] = gamma[f] * rsqrtf(mvar[f] + BN_EPS);
        off[j] = beta[f] - mmean[f] * inv[j];
    }

    for (int t = 0; t < TT; t++) {
        unsigned long long acc0[16], acc1[16];
#pragma unroll
        for (int m = 0; m < 16; m++) { acc0[m] = 0ull; acc1[m] = 0ull; }

        if (t > 0) {
            const float* hin = g_h[(t + 1) & 1] + (size_t)bb * FF * HH * WW;
            load_h_tile(s_in, hin, ty0, tx0, tid);
            load_tap_lstm(s_w, Wh, 0, fc, tid);
            __syncthreads();
#pragma unroll
            for (int tap = 0; tap < 9; tap++) {
                if (tap < 8)
                    load_tap_lstm(&s_w[((tap + 1) & 1) * 1024], Wh, tap + 1, fc, tid);
                conv_tap(s_in, &s_w[(tap & 1) * 1024], pr, px, tap / 3, tap % 3,
                         acc0, acc1);
                __syncthreads();
            }
        }

        float a0[32], a1[32];
#pragma unroll
        for (int m = 0; m < 16; m++) {
            unpack2(acc0[m], a0[2 * m], a0[2 * m + 1]);
            unpack2(acc1[m], a1[2 * m], a1[2 * m + 1]);
        }

        float* hbase = g_h[t & 1] + (size_t)bb * FF * HH * WW;

#pragma unroll
        for (int p = 0; p < 2; p++) {
            const float* a = p ? a1 : a0;
            const int gy = gy0 + p * 8;
            const size_t pix   = (size_t)bb * HH * WW + (size_t)gy * WW + gx;
            const size_t frame = (size_t)(bb * TT + t) * HH * WW + (size_t)gy * WW + gx;
            const float* xgp = &g_xg[frame * G4F];
            float* cst = &g_c[pix * FF + fc * 8];
            float* op  = &out[frame * FF + fc * 8];

            float coldv[8] = {0,0,0,0,0,0,0,0};
            if (t > 0) {
                float4 c0 = ((const float4*)cst)[0];
                float4 c1 = ((const float4*)cst)[1];
                coldv[0]=c0.x; coldv[1]=c0.y; coldv[2]=c0.z; coldv[3]=c0.w;
                coldv[4]=c1.x; coldv[5]=c1.y; coldv[6]=c1.z; coldv[7]=c1.w;
            }

            float cv[8], hv[8], ov[8];
#pragma unroll
            for (int j = 0; j < 8; j++) {
                int f = fc * 8 + j;
                float gi = a[0 * 8 + j] + __ldg(&xgp[0 * 32 + f]);
                float gf = a[1 * 8 + j] + __ldg(&xgp[1 * 32 + f]);
                float gc = a[2 * 8 + j] + __ldg(&xgp[2 * 32 + f]);
                float go = a[3 * 8 + j] + __ldg(&xgp[3 * 32 + f]);
                gi = hsig(gi); gf = hsig(gf); go = hsig(go);
                float cn = gf * coldv[j] + gi * tanhf(gc);
                float h  = go * tanhf(cn);
                cv[j] = cn; hv[j] = h;
                ov[j] = fmaf(h, inv[j], off[j]);
            }
            ((float4*)cst)[0] = make_float4(cv[0], cv[1], cv[2], cv[3]);
            ((float4*)cst)[1] = make_float4(cv[4], cv[5], cv[6], cv[7]);
            // transposed h store: per-channel coalesced STG.32
#pragma unroll
            for (int j = 0; j < 8; j++) {
                int f = fc * 8 + j;
                hbase[((size_t)f * HH + gy) * WW + gx] = hv[j];
            }
            ((float4*)op)[0]  = make_float4(ov[0], ov[1], ov[2], ov[3]);
            ((float4*)op)[1]  = make_float4(ov[4], ov[5], ov[6], ov[7]);
        }

        if (t < TT - 1) {
            __threadfence();
            __syncthreads();
            if (tid == 0) {
                atomicAdd(&g_bar[t], 1u);
                while (*((volatile unsigned*)&g_bar[t]) < (unsigned)LSTM_GRID)
                    __nanosleep(64);
            }
            __syncthreads();
            __threadfence();
        }
    }
}

// ===========================================================================
extern "C" void kernel_launch(void* const* d_in, const int* in_sizes, int n_in,
                              void* d_out, int out_size)
{
    const float* x     = (const float*)d_in[0];
    const float* Wx    = (const float*)d_in[1];
    const float* Wh    = (const float*)d_in[2];
    const float* b     = (const float*)d_in[3];
    const float* gamma = (const float*)d_in[4];
    const float* beta  = (const float*)d_in[5];
    const float* mmean = (const float*)d_in[6];
    const float* mvar  = (const float*)d_in[7];
    float* out = (float*)d_out;

    cudaFuncSetAttribute(xg_conv_kernel,
        cudaFuncAttributeMaxDynamicSharedMemorySize, SMEM_BYTES);
    cudaFuncSetAttribute(lstm_persistent,
        cudaFuncAttributeMaxDynamicSharedMemorySize, SMEM_BYTES);

    // 1) input-to-gate conv (R4 config + vectorized loader)
    {
        dim3 grid(8, 4, BB * TT);
        xg_conv_kernel<<<grid, 256, SMEM_BYTES>>>(x, Wx, b);
    }
    // 2) persistent recurrence (R4 config + transposed h)
    bar_reset_kernel<<<1, 32>>>();
    lstm_persistent<<<LSTM_GRID, 256, SMEM_BYTES>>>(
        Wh, gamma, beta, mmean, mvar, out);
}